// round 6
// baseline (speedup 1.0000x reference)
#include <cuda_runtime.h>
#include <math_constants.h>

#define B_  2
#define L_  2048
#define D_  1024
#define H_  16
#define DH_ 64

// Scratch for q, k, v projections ([B, L, D] each, fp32)
__device__ float g_q[B_ * L_ * D_];
__device__ float g_k[B_ * L_ * D_];
__device__ float g_v[B_ * L_ * D_];

// ---------------------------------------------------------------------------
// QKV projection: y = x @ W^T + b for W in {Wq, Wk, Wv} (blockIdx.z selects)
// Tiles: BM=BN=128, BK=16. 256 threads, 8x8 micro-tile per thread.
// SMEM stored k-major (transposed) so compute loads are contiguous LDS.128.
// ---------------------------------------------------------------------------
__global__ __launch_bounds__(256) void qkv_kernel(
    const float* __restrict__ x,
    const float* __restrict__ Wq, const float* __restrict__ bq,
    const float* __restrict__ Wk, const float* __restrict__ bk,
    const float* __restrict__ Wv, const float* __restrict__ bv)
{
    const float* W;
    const float* bias;
    float* out;
    if (blockIdx.z == 0)      { W = Wq; bias = bq; out = g_q; }
    else if (blockIdx.z == 1) { W = Wk; bias = bk; out = g_k; }
    else                      { W = Wv; bias = bv; out = g_v; }

    __shared__ float Xs[16][132];   // [k][m], padded to keep 16B alignment
    __shared__ float Ws[16][132];   // [k][n]

    const int m0  = blockIdx.y * 128;
    const int n0  = blockIdx.x * 128;
    const int tid = threadIdx.x;
    const int ty  = tid >> 4;       // 0..15
    const int tx  = tid & 15;       // 0..15

    float acc[8][8];
#pragma unroll
    for (int i = 0; i < 8; i++)
#pragma unroll
        for (int j = 0; j < 8; j++) acc[i][j] = 0.f;

    const int lrow = tid >> 1;          // 0..127
    const int lseg = (tid & 1) * 8;     // 0 or 8

    const float* xg = x + (size_t)(m0 + lrow) * D_ + lseg;
    const float* wg = W + (size_t)(n0 + lrow) * D_ + lseg;

    for (int k0 = 0; k0 < D_; k0 += 16) {
        float4 a0 = *(const float4*)(xg + k0);
        float4 a1 = *(const float4*)(xg + k0 + 4);
        float4 b0 = *(const float4*)(wg + k0);
        float4 b1 = *(const float4*)(wg + k0 + 4);
        __syncthreads();
        Xs[lseg + 0][lrow] = a0.x; Xs[lseg + 1][lrow] = a0.y;
        Xs[lseg + 2][lrow] = a0.z; Xs[lseg + 3][lrow] = a0.w;
        Xs[lseg + 4][lrow] = a1.x; Xs[lseg + 5][lrow] = a1.y;
        Xs[lseg + 6][lrow] = a1.z; Xs[lseg + 7][lrow] = a1.w;
        Ws[lseg + 0][lrow] = b0.x; Ws[lseg + 1][lrow] = b0.y;
        Ws[lseg + 2][lrow] = b0.z; Ws[lseg + 3][lrow] = b0.w;
        Ws[lseg + 4][lrow] = b1.x; Ws[lseg + 5][lrow] = b1.y;
        Ws[lseg + 6][lrow] = b1.z; Ws[lseg + 7][lrow] = b1.w;
        __syncthreads();
#pragma unroll
        for (int k = 0; k < 16; k++) {
            float af[8], bf[8];
            *(float4*)&af[0] = *(const float4*)&Xs[k][ty * 8];
            *(float4*)&af[4] = *(const float4*)&Xs[k][ty * 8 + 4];
            *(float4*)&bf[0] = *(const float4*)&Ws[k][tx * 8];
            *(float4*)&bf[4] = *(const float4*)&Ws[k][tx * 8 + 4];
#pragma unroll
            for (int i = 0; i < 8; i++)
#pragma unroll
                for (int j = 0; j < 8; j++)
                    acc[i][j] = fmaf(af[i], bf[j], acc[i][j]);
        }
    }

#pragma unroll
    for (int i = 0; i < 8; i++) {
        const int m = m0 + ty * 8 + i;
#pragma unroll
        for (int j = 0; j < 8; j += 4) {
            const int n = n0 + tx * 8 + j;
            float4 r;
            r.x = acc[i][j + 0] + bias[n + 0];
            r.y = acc[i][j + 1] + bias[n + 1];
            r.z = acc[i][j + 2] + bias[n + 2];
            r.w = acc[i][j + 3] + bias[n + 3];
            *(float4*)&out[(size_t)m * D_ + n] = r;
        }
    }
}

// ---------------------------------------------------------------------------
// Causal flash attention. 64x64 tiles, DH=64. 256 threads = 16x16, each thread
// owns a 4x4 score/output micro-tile. Online softmax; 16-lane shfl reductions.
// Each CTA processes query blocks {x, 31-x} -> exactly 33 KV tiles per CTA.
// ---------------------------------------------------------------------------
__global__ __launch_bounds__(256) void attn_kernel(float* __restrict__ out)
{
    extern __shared__ float sm[];
    float* Qs = sm;                 // [d][r]  64 x 68 (scaled by 1/8)
    float* Ks = sm + 64 * 68;       // [d][c]  64 x 68
    float* Vs = sm + 2 * 64 * 68;   // [c][dv] 64 x 68
    float* Ps = sm + 3 * 64 * 68;   // [c][r]  64 x 68

    const int bh = blockIdx.y;
    const int b  = bh >> 4;
    const int h  = bh & 15;
    const int tid = threadIdx.x;
    const int ty  = tid >> 4;       // 0..15
    const int tx  = tid & 15;       // 0..15

    const size_t base = (size_t)b * L_ * D_ + (size_t)h * DH_;

    const int lr = tid >> 2;            // 0..63 (row for tile loads)
    const int ld0 = (tid & 3) * 16;     // 0,16,32,48

    for (int pass = 0; pass < 2; pass++) {
        const int qb = (pass == 0) ? (int)blockIdx.x : (31 - (int)blockIdx.x);
        const int q0 = qb * 64;

        __syncthreads();  // previous pass finished with all SMEM
        // Load Q tile (scaled), transposed into [d][r]
        {
            const float* qg = g_q + base + (size_t)(q0 + lr) * D_ + ld0;
#pragma unroll
            for (int u = 0; u < 4; u++) {
                float4 v = *(const float4*)(qg + u * 4);
                Qs[(ld0 + u * 4 + 0) * 68 + lr] = v.x * 0.125f;
                Qs[(ld0 + u * 4 + 1) * 68 + lr] = v.y * 0.125f;
                Qs[(ld0 + u * 4 + 2) * 68 + lr] = v.z * 0.125f;
                Qs[(ld0 + u * 4 + 3) * 68 + lr] = v.w * 0.125f;
            }
        }

        float o[4][4];
        float mrow[4], lrow[4];
#pragma unroll
        for (int i = 0; i < 4; i++) {
            mrow[i] = -CUDART_INF_F;
            lrow[i] = 0.f;
#pragma unroll
            for (int j = 0; j < 4; j++) o[i][j] = 0.f;
        }

        for (int kb = 0; kb <= qb; kb++) {
            const int k0 = kb * 64;
            __syncthreads();  // prior tile consumers done (also covers Q store on kb=0)
            // Load K transposed [d][c], V direct [c][dv]
            {
                const float* kg = g_k + base + (size_t)(k0 + lr) * D_ + ld0;
                const float* vg = g_v + base + (size_t)(k0 + lr) * D_ + ld0;
#pragma unroll
                for (int u = 0; u < 4; u++) {
                    float4 kv = *(const float4*)(kg + u * 4);
                    Ks[(ld0 + u * 4 + 0) * 68 + lr] = kv.x;
                    Ks[(ld0 + u * 4 + 1) * 68 + lr] = kv.y;
                    Ks[(ld0 + u * 4 + 2) * 68 + lr] = kv.z;
                    Ks[(ld0 + u * 4 + 3) * 68 + lr] = kv.w;
                    float4 vv = *(const float4*)(vg + u * 4);
                    *(float4*)&Vs[lr * 68 + ld0 + u * 4] = vv;
                }
            }
            __syncthreads();

            // S = (Q/8) @ K^T  (4x4 per thread, reduce over d=64)
            float s[4][4];
#pragma unroll
            for (int i = 0; i < 4; i++)
#pragma unroll
                for (int j = 0; j < 4; j++) s[i][j] = 0.f;
#pragma unroll
            for (int d = 0; d < 64; d++) {
                float4 a = *(const float4*)&Qs[d * 68 + ty * 4];
                float4 bb = *(const float4*)&Ks[d * 68 + tx * 4];
                const float af[4] = {a.x, a.y, a.z, a.w};
                const float bf[4] = {bb.x, bb.y, bb.z, bb.w};
#pragma unroll
                for (int i = 0; i < 4; i++)
#pragma unroll
                    for (int j = 0; j < 4; j++)
                        s[i][j] = fmaf(af[i], bf[j], s[i][j]);
            }

            // Causal mask (only the diagonal tile needs it)
            if (kb == qb) {
#pragma unroll
                for (int i = 0; i < 4; i++) {
                    const int qr = q0 + ty * 4 + i;
#pragma unroll
                    for (int j = 0; j < 4; j++) {
                        const int kc = k0 + tx * 4 + j;
                        if (kc > qr) s[i][j] = -CUDART_INF_F;
                    }
                }
            }

            // Online softmax update
#pragma unroll
            for (int i = 0; i < 4; i++) {
                float mx = fmaxf(fmaxf(s[i][0], s[i][1]), fmaxf(s[i][2], s[i][3]));
                mx = fmaxf(mx, __shfl_xor_sync(0xffffffffu, mx, 1));
                mx = fmaxf(mx, __shfl_xor_sync(0xffffffffu, mx, 2));
                mx = fmaxf(mx, __shfl_xor_sync(0xffffffffu, mx, 4));
                mx = fmaxf(mx, __shfl_xor_sync(0xffffffffu, mx, 8));
                const float mn = fmaxf(mrow[i], mx);
                const float cf = __expf(mrow[i] - mn);   // 0 on first tile
                mrow[i] = mn;
                float rs = 0.f;
#pragma unroll
                for (int j = 0; j < 4; j++) {
                    s[i][j] = __expf(s[i][j] - mn);
                    rs += s[i][j];
                }
                rs += __shfl_xor_sync(0xffffffffu, rs, 1);
                rs += __shfl_xor_sync(0xffffffffu, rs, 2);
                rs += __shfl_xor_sync(0xffffffffu, rs, 4);
                rs += __shfl_xor_sync(0xffffffffu, rs, 8);
                lrow[i] = lrow[i] * cf + rs;
#pragma unroll
                for (int j = 0; j < 4; j++) o[i][j] *= cf;
            }

            // Store P transposed [c][r]
#pragma unroll
            for (int i = 0; i < 4; i++)
#pragma unroll
                for (int j = 0; j < 4; j++)
                    Ps[(tx * 4 + j) * 68 + (ty * 4 + i)] = s[i][j];
            __syncthreads();

            // O += P @ V (reduce over c=64)
#pragma unroll
            for (int c = 0; c < 64; c++) {
                float4 a = *(const float4*)&Ps[c * 68 + ty * 4];
                float4 bb = *(const float4*)&Vs[c * 68 + tx * 4];
                const float af[4] = {a.x, a.y, a.z, a.w};
                const float bf[4] = {bb.x, bb.y, bb.z, bb.w};
#pragma unroll
                for (int i = 0; i < 4; i++)
#pragma unroll
                    for (int j = 0; j < 4; j++)
                        o[i][j] = fmaf(af[i], bf[j], o[i][j]);
            }
        }

        // Epilogue: normalize and write [B, L, H*DH]
#pragma unroll
        for (int i = 0; i < 4; i++) {
            const float inv = 1.f / lrow[i];
            float4 r4;
            r4.x = o[i][0] * inv;
            r4.y = o[i][1] * inv;
            r4.z = o[i][2] * inv;
            r4.w = o[i][3] * inv;
            *(float4*)&out[base + (size_t)(q0 + ty * 4 + i) * D_ + tx * 4] = r4;
        }
    }
}

// ---------------------------------------------------------------------------
extern "C" void kernel_launch(void* const* d_in, const int* in_sizes, int n_in,
                              void* d_out, int out_size)
{
    const float* x  = (const float*)d_in[0];
    // d_in[1] = atten_mask (strict upper triangular; computed analytically, unused)
    const float* Wq = (const float*)d_in[2];
    const float* bq = (const float*)d_in[3];
    const float* Wk = (const float*)d_in[4];
    const float* bk = (const float*)d_in[5];
    const float* Wv = (const float*)d_in[6];
    const float* bv = (const float*)d_in[7];
    float* out = (float*)d_out;

    qkv_kernel<<<dim3(D_ / 128, (B_ * L_) / 128, 3), 256>>>(x, Wq, bq, Wk, bk, Wv, bv);

    const int smem = 4 * 64 * 68 * (int)sizeof(float);  // 69632 B
    cudaFuncSetAttribute(attn_kernel, cudaFuncAttributeMaxDynamicSharedMemorySize, smem);
    attn_kernel<<<dim3(L_ / 64 / 2, B_ * H_), 256, smem>>>(out);
}

// round 7
// speedup vs baseline: 1.0010x; 1.0010x over previous
#include <cuda_runtime.h>
#include <math_constants.h>

#define B_  2
#define L_  2048
#define D_  1024
#define H_  16
#define DH_ 64

// Scratch for q, k, v projections ([B, L, D] each, fp32)
__device__ float g_q[B_ * L_ * D_];
__device__ float g_k[B_ * L_ * D_];
__device__ float g_v[B_ * L_ * D_];

// ---------------------------------------------------------------------------
// QKV projection: y = x @ W^T + b for W in {Wq, Wk, Wv} (blockIdx.z selects)
// Tiles: BM=BN=128, BK=16. 256 threads, 8x8 micro-tile per thread.
// SMEM stored k-major (transposed) so compute loads are contiguous LDS.128.
// ---------------------------------------------------------------------------
__global__ __launch_bounds__(256) void qkv_kernel(
    const float* __restrict__ x,
    const float* __restrict__ Wq, const float* __restrict__ bq,
    const float* __restrict__ Wk, const float* __restrict__ bk,
    const float* __restrict__ Wv, const float* __restrict__ bv)
{
    const float* W;
    const float* bias;
    float* out;
    if (blockIdx.z == 0)      { W = Wq; bias = bq; out = g_q; }
    else if (blockIdx.z == 1) { W = Wk; bias = bk; out = g_k; }
    else                      { W = Wv; bias = bv; out = g_v; }

    __shared__ float Xs[16][132];   // [k][m], padded to keep 16B alignment
    __shared__ float Ws[16][132];   // [k][n]

    const int m0  = blockIdx.y * 128;
    const int n0  = blockIdx.x * 128;
    const int tid = threadIdx.x;
    const int ty  = tid >> 4;       // 0..15
    const int tx  = tid & 15;       // 0..15

    float acc[8][8];
#pragma unroll
    for (int i = 0; i < 8; i++)
#pragma unroll
        for (int j = 0; j < 8; j++) acc[i][j] = 0.f;

    const int lrow = tid >> 1;          // 0..127
    const int lseg = (tid & 1) * 8;     // 0 or 8

    const float* xg = x + (size_t)(m0 + lrow) * D_ + lseg;
    const float* wg = W + (size_t)(n0 + lrow) * D_ + lseg;

    for (int k0 = 0; k0 < D_; k0 += 16) {
        float4 a0 = *(const float4*)(xg + k0);
        float4 a1 = *(const float4*)(xg + k0 + 4);
        float4 b0 = *(const float4*)(wg + k0);
        float4 b1 = *(const float4*)(wg + k0 + 4);
        __syncthreads();
        Xs[lseg + 0][lrow] = a0.x; Xs[lseg + 1][lrow] = a0.y;
        Xs[lseg + 2][lrow] = a0.z; Xs[lseg + 3][lrow] = a0.w;
        Xs[lseg + 4][lrow] = a1.x; Xs[lseg + 5][lrow] = a1.y;
        Xs[lseg + 6][lrow] = a1.z; Xs[lseg + 7][lrow] = a1.w;
        Ws[lseg + 0][lrow] = b0.x; Ws[lseg + 1][lrow] = b0.y;
        Ws[lseg + 2][lrow] = b0.z; Ws[lseg + 3][lrow] = b0.w;
        Ws[lseg + 4][lrow] = b1.x; Ws[lseg + 5][lrow] = b1.y;
        Ws[lseg + 6][lrow] = b1.z; Ws[lseg + 7][lrow] = b1.w;
        __syncthreads();
#pragma unroll
        for (int k = 0; k < 16; k++) {
            float af[8], bf[8];
            *(float4*)&af[0] = *(const float4*)&Xs[k][ty * 8];
            *(float4*)&af[4] = *(const float4*)&Xs[k][ty * 8 + 4];
            *(float4*)&bf[0] = *(const float4*)&Ws[k][tx * 8];
            *(float4*)&bf[4] = *(const float4*)&Ws[k][tx * 8 + 4];
#pragma unroll
            for (int i = 0; i < 8; i++)
#pragma unroll
                for (int j = 0; j < 8; j++)
                    acc[i][j] = fmaf(af[i], bf[j], acc[i][j]);
        }
    }

#pragma unroll
    for (int i = 0; i < 8; i++) {
        const int m = m0 + ty * 8 + i;
#pragma unroll
        for (int j = 0; j < 8; j += 4) {
            const int n = n0 + tx * 8 + j;
            float4 r;
            r.x = acc[i][j + 0] + bias[n + 0];
            r.y = acc[i][j + 1] + bias[n + 1];
            r.z = acc[i][j + 2] + bias[n + 2];
            r.w = acc[i][j + 3] + bias[n + 3];
            *(float4*)&out[(size_t)m * D_ + n] = r;
        }
    }
}

// ---------------------------------------------------------------------------
// Causal flash attention. 64x64 tiles, DH=64. 256 threads = 16x16, each thread
// owns a 4x4 score/output micro-tile. Online softmax; 16-lane shfl reductions.
// Each CTA processes query blocks {x, 31-x} -> exactly 33 KV tiles per CTA.
// ---------------------------------------------------------------------------
__global__ __launch_bounds__(256) void attn_kernel(float* __restrict__ out)
{
    extern __shared__ float sm[];
    float* Qs = sm;                 // [d][r]  64 x 68 (scaled by 1/8)
    float* Ks = sm + 64 * 68;       // [d][c]  64 x 68
    float* Vs = sm + 2 * 64 * 68;   // [c][dv] 64 x 68
    float* Ps = sm + 3 * 64 * 68;   // [c][r]  64 x 68

    const int bh = blockIdx.y;
    const int b  = bh >> 4;
    const int h  = bh & 15;
    const int tid = threadIdx.x;
    const int ty  = tid >> 4;       // 0..15
    const int tx  = tid & 15;       // 0..15

    const size_t base = (size_t)b * L_ * D_ + (size_t)h * DH_;

    const int lr = tid >> 2;            // 0..63 (row for tile loads)
    const int ld0 = (tid & 3) * 16;     // 0,16,32,48

    for (int pass = 0; pass < 2; pass++) {
        const int qb = (pass == 0) ? (int)blockIdx.x : (31 - (int)blockIdx.x);
        const int q0 = qb * 64;

        __syncthreads();  // previous pass finished with all SMEM
        // Load Q tile (scaled), transposed into [d][r]
        {
            const float* qg = g_q + base + (size_t)(q0 + lr) * D_ + ld0;
#pragma unroll
            for (int u = 0; u < 4; u++) {
                float4 v = *(const float4*)(qg + u * 4);
                Qs[(ld0 + u * 4 + 0) * 68 + lr] = v.x * 0.125f;
                Qs[(ld0 + u * 4 + 1) * 68 + lr] = v.y * 0.125f;
                Qs[(ld0 + u * 4 + 2) * 68 + lr] = v.z * 0.125f;
                Qs[(ld0 + u * 4 + 3) * 68 + lr] = v.w * 0.125f;
            }
        }

        float o[4][4];
        float mrow[4], lrow[4];
#pragma unroll
        for (int i = 0; i < 4; i++) {
            mrow[i] = -CUDART_INF_F;
            lrow[i] = 0.f;
#pragma unroll
            for (int j = 0; j < 4; j++) o[i][j] = 0.f;
        }

        for (int kb = 0; kb <= qb; kb++) {
            const int k0 = kb * 64;
            __syncthreads();  // prior tile consumers done (also covers Q store on kb=0)
            // Load K transposed [d][c], V direct [c][dv]
            {
                const float* kg = g_k + base + (size_t)(k0 + lr) * D_ + ld0;
                const float* vg = g_v + base + (size_t)(k0 + lr) * D_ + ld0;
#pragma unroll
                for (int u = 0; u < 4; u++) {
                    float4 kv = *(const float4*)(kg + u * 4);
                    Ks[(ld0 + u * 4 + 0) * 68 + lr] = kv.x;
                    Ks[(ld0 + u * 4 + 1) * 68 + lr] = kv.y;
                    Ks[(ld0 + u * 4 + 2) * 68 + lr] = kv.z;
                    Ks[(ld0 + u * 4 + 3) * 68 + lr] = kv.w;
                    float4 vv = *(const float4*)(vg + u * 4);
                    *(float4*)&Vs[lr * 68 + ld0 + u * 4] = vv;
                }
            }
            __syncthreads();

            // S = (Q/8) @ K^T  (4x4 per thread, reduce over d=64)
            float s[4][4];
#pragma unroll
            for (int i = 0; i < 4; i++)
#pragma unroll
                for (int j = 0; j < 4; j++) s[i][j] = 0.f;
#pragma unroll
            for (int d = 0; d < 64; d++) {
                float4 a = *(const float4*)&Qs[d * 68 + ty * 4];
                float4 bb = *(const float4*)&Ks[d * 68 + tx * 4];
                const float af[4] = {a.x, a.y, a.z, a.w};
                const float bf[4] = {bb.x, bb.y, bb.z, bb.w};
#pragma unroll
                for (int i = 0; i < 4; i++)
#pragma unroll
                    for (int j = 0; j < 4; j++)
                        s[i][j] = fmaf(af[i], bf[j], s[i][j]);
            }

            // Causal mask (only the diagonal tile needs it)
            if (kb == qb) {
#pragma unroll
                for (int i = 0; i < 4; i++) {
                    const int qr = q0 + ty * 4 + i;
#pragma unroll
                    for (int j = 0; j < 4; j++) {
                        const int kc = k0 + tx * 4 + j;
                        if (kc > qr) s[i][j] = -CUDART_INF_F;
                    }
                }
            }

            // Online softmax update
#pragma unroll
            for (int i = 0; i < 4; i++) {
                float mx = fmaxf(fmaxf(s[i][0], s[i][1]), fmaxf(s[i][2], s[i][3]));
                mx = fmaxf(mx, __shfl_xor_sync(0xffffffffu, mx, 1));
                mx = fmaxf(mx, __shfl_xor_sync(0xffffffffu, mx, 2));
                mx = fmaxf(mx, __shfl_xor_sync(0xffffffffu, mx, 4));
                mx = fmaxf(mx, __shfl_xor_sync(0xffffffffu, mx, 8));
                const float mn = fmaxf(mrow[i], mx);
                const float cf = __expf(mrow[i] - mn);   // 0 on first tile
                mrow[i] = mn;
                float rs = 0.f;
#pragma unroll
                for (int j = 0; j < 4; j++) {
                    s[i][j] = __expf(s[i][j] - mn);
                    rs += s[i][j];
                }
                rs += __shfl_xor_sync(0xffffffffu, rs, 1);
                rs += __shfl_xor_sync(0xffffffffu, rs, 2);
                rs += __shfl_xor_sync(0xffffffffu, rs, 4);
                rs += __shfl_xor_sync(0xffffffffu, rs, 8);
                lrow[i] = lrow[i] * cf + rs;
#pragma unroll
                for (int j = 0; j < 4; j++) o[i][j] *= cf;
            }

            // Store P transposed [c][r]
#pragma unroll
            for (int i = 0; i < 4; i++)
#pragma unroll
                for (int j = 0; j < 4; j++)
                    Ps[(tx * 4 + j) * 68 + (ty * 4 + i)] = s[i][j];
            __syncthreads();

            // O += P @ V (reduce over c=64)
#pragma unroll
            for (int c = 0; c < 64; c++) {
                float4 a = *(const float4*)&Ps[c * 68 + ty * 4];
                float4 bb = *(const float4*)&Vs[c * 68 + tx * 4];
                const float af[4] = {a.x, a.y, a.z, a.w};
                const float bf[4] = {bb.x, bb.y, bb.z, bb.w};
#pragma unroll
                for (int i = 0; i < 4; i++)
#pragma unroll
                    for (int j = 0; j < 4; j++)
                        o[i][j] = fmaf(af[i], bf[j], o[i][j]);
            }
        }

        // Epilogue: normalize and write [B, L, H*DH]
#pragma unroll
        for (int i = 0; i < 4; i++) {
            const float inv = 1.f / lrow[i];
            float4 r4;
            r4.x = o[i][0] * inv;
            r4.y = o[i][1] * inv;
            r4.z = o[i][2] * inv;
            r4.w = o[i][3] * inv;
            *(float4*)&out[base + (size_t)(q0 + ty * 4 + i) * D_ + tx * 4] = r4;
        }
    }
}

// ---------------------------------------------------------------------------
extern "C" void kernel_launch(void* const* d_in, const int* in_sizes, int n_in,
                              void* d_out, int out_size)
{
    const float* x  = (const float*)d_in[0];
    // d_in[1] = atten_mask (strict upper triangular; computed analytically, unused)
    const float* Wq = (const float*)d_in[2];
    const float* bq = (const float*)d_in[3];
    const float* Wk = (const float*)d_in[4];
    const float* bk = (const float*)d_in[5];
    const float* Wv = (const float*)d_in[6];
    const float* bv = (const float*)d_in[7];
    float* out = (float*)d_out;

    qkv_kernel<<<dim3(D_ / 128, (B_ * L_) / 128, 3), 256>>>(x, Wq, bq, Wk, bk, Wv, bv);

    const int smem = 4 * 64 * 68 * (int)sizeof(float);  // 69632 B
    cudaFuncSetAttribute(attn_kernel, cudaFuncAttributeMaxDynamicSharedMemorySize, smem);
    attn_kernel<<<dim3(L_ / 64 / 2, B_ * H_), 256, smem>>>(out);
}

// round 8
// speedup vs baseline: 1.4047x; 1.4033x over previous
#include <cuda_runtime.h>
#include <cuda_bf16.h>
#include <math_constants.h>
#include <cstdint>

#define B_  2
#define L_  2048
#define D_  1024
#define H_  16
#define DH_ 64

// Scratch for q, k, v projections ([B, L, D] each, fp32)
__device__ float g_q[B_ * L_ * D_];
__device__ float g_k[B_ * L_ * D_];
__device__ float g_v[B_ * L_ * D_];

// Split-precision bf16 operands (hi + lo capture ~16 mantissa bits of fp32)
__device__ __align__(16) __nv_bfloat16 g_xh[B_ * L_ * D_];
__device__ __align__(16) __nv_bfloat16 g_xl[B_ * L_ * D_];
__device__ __align__(16) __nv_bfloat16 g_wh[3 * D_ * D_];
__device__ __align__(16) __nv_bfloat16 g_wl[3 * D_ * D_];

// ---------------------------------------------------------------------------
// Decompose fp32 -> (bf16 hi, bf16 lo) for x and the three weight matrices.
// ---------------------------------------------------------------------------
__global__ __launch_bounds__(256) void decomp_kernel(
    const float* __restrict__ x,
    const float* __restrict__ Wq,
    const float* __restrict__ Wk,
    const float* __restrict__ Wv)
{
    const int NX = B_ * L_ * D_ / 4;   // float4 counts
    const int NW = D_ * D_ / 4;
    int i = blockIdx.x * 256 + threadIdx.x;

    const float* src;
    __nv_bfloat16 *dh, *dl;
    int off;
    if (i < NX)               { src = x;  dh = g_xh;             dl = g_xl;             off = i; }
    else if (i < NX + NW)     { src = Wq; dh = g_wh;             dl = g_wl;             off = i - NX; }
    else if (i < NX + 2 * NW) { src = Wk; dh = g_wh + D_ * D_;   dl = g_wl + D_ * D_;   off = i - NX - NW; }
    else                      { src = Wv; dh = g_wh + 2*D_*D_;   dl = g_wl + 2*D_*D_;   off = i - NX - 2 * NW; }

    float4 v = ((const float4*)src)[off];
    float vs[4] = {v.x, v.y, v.z, v.w};
    __nv_bfloat16 h[4], l[4];
#pragma unroll
    for (int j = 0; j < 4; j++) {
        h[j] = __float2bfloat16(vs[j]);
        l[j] = __float2bfloat16(vs[j] - __bfloat162float(h[j]));
    }
    __nv_bfloat162 h01, h23, l01, l23;
    h01.x = h[0]; h01.y = h[1]; h23.x = h[2]; h23.y = h[3];
    l01.x = l[0]; l01.y = l[1]; l23.x = l[2]; l23.y = l[3];
    ((__nv_bfloat162*)dh)[off * 2 + 0] = h01;
    ((__nv_bfloat162*)dh)[off * 2 + 1] = h23;
    ((__nv_bfloat162*)dl)[off * 2 + 0] = l01;
    ((__nv_bfloat162*)dl)[off * 2 + 1] = l23;
}

// ---------------------------------------------------------------------------
// Tensor-core QKV GEMM: y = x @ W^T + b via mma.sync m16n8k16 bf16, with
// split-precision 3-product accumulation (hh + hl + lh) for fp32-level accuracy.
// Block tile 128x128x32, 8 warps of 64x32.
// ---------------------------------------------------------------------------
__device__ __forceinline__ uint32_t sptr(const void* p)
{
    return (uint32_t)__cvta_generic_to_shared(p);
}

#define LDSM4(r, addr) \
    asm volatile("ldmatrix.sync.aligned.m8n8.x4.shared.b16 {%0,%1,%2,%3}, [%4];" \
                 : "=r"((r)[0]), "=r"((r)[1]), "=r"((r)[2]), "=r"((r)[3]) : "r"(addr))

#define LDSM2(r, addr) \
    asm volatile("ldmatrix.sync.aligned.m8n8.x2.shared.b16 {%0,%1}, [%2];" \
                 : "=r"((r)[0]), "=r"((r)[1]) : "r"(addr))

#define MMA16816(d, a, b) \
    asm volatile("mma.sync.aligned.m16n8k16.row.col.f32.bf16.bf16.f32 " \
                 "{%0,%1,%2,%3}, {%4,%5,%6,%7}, {%8,%9}, {%0,%1,%2,%3};" \
                 : "+f"((d)[0]), "+f"((d)[1]), "+f"((d)[2]), "+f"((d)[3]) \
                 : "r"((a)[0]), "r"((a)[1]), "r"((a)[2]), "r"((a)[3]), \
                   "r"((b)[0]), "r"((b)[1]))

__global__ __launch_bounds__(256) void qkv_mma_kernel(
    const float* __restrict__ bq,
    const float* __restrict__ bk_,
    const float* __restrict__ bv)
{
    const int z = blockIdx.z;
    const __nv_bfloat16* Wh = g_wh + (size_t)z * D_ * D_;
    const __nv_bfloat16* Wl = g_wl + (size_t)z * D_ * D_;
    const float* bias = (z == 0) ? bq : (z == 1) ? bk_ : bv;
    float* out = (z == 0) ? g_q : (z == 1) ? g_k : g_v;

    __shared__ __nv_bfloat16 sXh[128][40];  // [m][k], +8 pad -> conflict-free ldmatrix
    __shared__ __nv_bfloat16 sXl[128][40];
    __shared__ __nv_bfloat16 sWh[128][40];  // [n][k]
    __shared__ __nv_bfloat16 sWl[128][40];

    const int tid  = threadIdx.x;
    const int warp = tid >> 5;
    const int lane = tid & 31;
    const int wm   = (warp & 1) * 64;      // warp m-offset within block
    const int wn   = (warp >> 1) * 32;     // warp n-offset within block
    const int m0   = blockIdx.y * 128;
    const int n0   = blockIdx.x * 128;

    float acc[4][4][4];
#pragma unroll
    for (int i = 0; i < 4; i++)
#pragma unroll
        for (int j = 0; j < 4; j++)
#pragma unroll
            for (int c = 0; c < 4; c++) acc[i][j][c] = 0.f;

    // Each thread loads 2x uint4 (16 bf16) per array per K-iter
    const int lrow = tid >> 1;          // 0..127
    const int ls   = (tid & 1) * 16;    // bf16 offset 0 or 16

    const __nv_bfloat16* xh_g = g_xh + (size_t)(m0 + lrow) * D_ + ls;
    const __nv_bfloat16* xl_g = g_xl + (size_t)(m0 + lrow) * D_ + ls;
    const __nv_bfloat16* wh_g = Wh   + (size_t)(n0 + lrow) * D_ + ls;
    const __nv_bfloat16* wl_g = Wl   + (size_t)(n0 + lrow) * D_ + ls;

    for (int k0 = 0; k0 < D_; k0 += 32) {
        uint4 v0 = *(const uint4*)(xh_g + k0);
        uint4 v1 = *(const uint4*)(xh_g + k0 + 8);
        uint4 v2 = *(const uint4*)(xl_g + k0);
        uint4 v3 = *(const uint4*)(xl_g + k0 + 8);
        uint4 v4 = *(const uint4*)(wh_g + k0);
        uint4 v5 = *(const uint4*)(wh_g + k0 + 8);
        uint4 v6 = *(const uint4*)(wl_g + k0);
        uint4 v7 = *(const uint4*)(wl_g + k0 + 8);
        __syncthreads();
        *(uint4*)&sXh[lrow][ls]     = v0;
        *(uint4*)&sXh[lrow][ls + 8] = v1;
        *(uint4*)&sXl[lrow][ls]     = v2;
        *(uint4*)&sXl[lrow][ls + 8] = v3;
        *(uint4*)&sWh[lrow][ls]     = v4;
        *(uint4*)&sWh[lrow][ls + 8] = v5;
        *(uint4*)&sWl[lrow][ls]     = v6;
        *(uint4*)&sWl[lrow][ls + 8] = v7;
        __syncthreads();

#pragma unroll
        for (int ks = 0; ks < 2; ks++) {
            uint32_t ah[4][4], al[4][4], bh[4][2], bl[4][2];
            const int acol = ks * 16 + (lane >> 4) * 8;
            const int bcol = ks * 16 + ((lane >> 3) & 1) * 8;
#pragma unroll
            for (int i = 0; i < 4; i++) {
                const int ar = wm + i * 16 + (lane & 15);
                LDSM4(ah[i], sptr(&sXh[ar][acol]));
                LDSM4(al[i], sptr(&sXl[ar][acol]));
            }
#pragma unroll
            for (int j = 0; j < 4; j++) {
                const int br = wn + j * 8 + (lane & 7);
                LDSM2(bh[j], sptr(&sWh[br][bcol]));
                LDSM2(bl[j], sptr(&sWl[br][bcol]));
            }
#pragma unroll
            for (int i = 0; i < 4; i++)
#pragma unroll
                for (int j = 0; j < 4; j++) {
                    MMA16816(acc[i][j], ah[i], bh[j]);
                    MMA16816(acc[i][j], ah[i], bl[j]);
                    MMA16816(acc[i][j], al[i], bh[j]);
                }
        }
    }

    // Epilogue: add bias, write fp32
#pragma unroll
    for (int i = 0; i < 4; i++) {
        const int r0 = m0 + wm + i * 16 + (lane >> 2);
#pragma unroll
        for (int j = 0; j < 4; j++) {
            const int c = n0 + wn + j * 8 + (lane & 3) * 2;
            const float2 bb = *(const float2*)&bias[c];
            float2 o0, o1;
            o0.x = acc[i][j][0] + bb.x;
            o0.y = acc[i][j][1] + bb.y;
            o1.x = acc[i][j][2] + bb.x;
            o1.y = acc[i][j][3] + bb.y;
            *(float2*)&out[(size_t)r0 * D_ + c]       = o0;
            *(float2*)&out[(size_t)(r0 + 8) * D_ + c] = o1;
        }
    }
}

// ---------------------------------------------------------------------------
// Causal flash attention (unchanged from R7). 64x64 tiles, DH=64, fp32.
// ---------------------------------------------------------------------------
__global__ __launch_bounds__(256) void attn_kernel(float* __restrict__ out)
{
    extern __shared__ float sm[];
    float* Qs = sm;                 // [d][r]  64 x 68 (scaled by 1/8)
    float* Ks = sm + 64 * 68;       // [d][c]  64 x 68
    float* Vs = sm + 2 * 64 * 68;   // [c][dv] 64 x 68
    float* Ps = sm + 3 * 64 * 68;   // [c][r]  64 x 68

    const int bh = blockIdx.y;
    const int b  = bh >> 4;
    const int h  = bh & 15;
    const int tid = threadIdx.x;
    const int ty  = tid >> 4;
    const int tx  = tid & 15;

    const size_t base = (size_t)b * L_ * D_ + (size_t)h * DH_;

    const int lr  = tid >> 2;
    const int ld0 = (tid & 3) * 16;

    for (int pass = 0; pass < 2; pass++) {
        const int qb = (pass == 0) ? (int)blockIdx.x : (31 - (int)blockIdx.x);
        const int q0 = qb * 64;

        __syncthreads();
        {
            const float* qg = g_q + base + (size_t)(q0 + lr) * D_ + ld0;
#pragma unroll
            for (int u = 0; u < 4; u++) {
                float4 v = *(const float4*)(qg + u * 4);
                Qs[(ld0 + u * 4 + 0) * 68 + lr] = v.x * 0.125f;
                Qs[(ld0 + u * 4 + 1) * 68 + lr] = v.y * 0.125f;
                Qs[(ld0 + u * 4 + 2) * 68 + lr] = v.z * 0.125f;
                Qs[(ld0 + u * 4 + 3) * 68 + lr] = v.w * 0.125f;
            }
        }

        float o[4][4];
        float mrow[4], lrow[4];
#pragma unroll
        for (int i = 0; i < 4; i++) {
            mrow[i] = -CUDART_INF_F;
            lrow[i] = 0.f;
#pragma unroll
            for (int j = 0; j < 4; j++) o[i][j] = 0.f;
        }

        for (int kb = 0; kb <= qb; kb++) {
            const int k0 = kb * 64;
            __syncthreads();
            {
                const float* kg = g_k + base + (size_t)(k0 + lr) * D_ + ld0;
                const float* vg = g_v + base + (size_t)(k0 + lr) * D_ + ld0;
#pragma unroll
                for (int u = 0; u < 4; u++) {
                    float4 kv = *(const float4*)(kg + u * 4);
                    Ks[(ld0 + u * 4 + 0) * 68 + lr] = kv.x;
                    Ks[(ld0 + u * 4 + 1) * 68 + lr] = kv.y;
                    Ks[(ld0 + u * 4 + 2) * 68 + lr] = kv.z;
                    Ks[(ld0 + u * 4 + 3) * 68 + lr] = kv.w;
                    float4 vv = *(const float4*)(vg + u * 4);
                    *(float4*)&Vs[lr * 68 + ld0 + u * 4] = vv;
                }
            }
            __syncthreads();

            float s[4][4];
#pragma unroll
            for (int i = 0; i < 4; i++)
#pragma unroll
                for (int j = 0; j < 4; j++) s[i][j] = 0.f;
#pragma unroll
            for (int d = 0; d < 64; d++) {
                float4 a  = *(const float4*)&Qs[d * 68 + ty * 4];
                float4 bb = *(const float4*)&Ks[d * 68 + tx * 4];
                const float af[4] = {a.x, a.y, a.z, a.w};
                const float bf[4] = {bb.x, bb.y, bb.z, bb.w};
#pragma unroll
                for (int i = 0; i < 4; i++)
#pragma unroll
                    for (int j = 0; j < 4; j++)
                        s[i][j] = fmaf(af[i], bf[j], s[i][j]);
            }

            if (kb == qb) {
#pragma unroll
                for (int i = 0; i < 4; i++) {
                    const int qr = q0 + ty * 4 + i;
#pragma unroll
                    for (int j = 0; j < 4; j++) {
                        const int kc = k0 + tx * 4 + j;
                        if (kc > qr) s[i][j] = -CUDART_INF_F;
                    }
                }
            }

#pragma unroll
            for (int i = 0; i < 4; i++) {
                float mx = fmaxf(fmaxf(s[i][0], s[i][1]), fmaxf(s[i][2], s[i][3]));
                mx = fmaxf(mx, __shfl_xor_sync(0xffffffffu, mx, 1));
                mx = fmaxf(mx, __shfl_xor_sync(0xffffffffu, mx, 2));
                mx = fmaxf(mx, __shfl_xor_sync(0xffffffffu, mx, 4));
                mx = fmaxf(mx, __shfl_xor_sync(0xffffffffu, mx, 8));
                const float mn = fmaxf(mrow[i], mx);
                const float cf = __expf(mrow[i] - mn);
                mrow[i] = mn;
                float rs = 0.f;
#pragma unroll
                for (int j = 0; j < 4; j++) {
                    s[i][j] = __expf(s[i][j] - mn);
                    rs += s[i][j];
                }
                rs += __shfl_xor_sync(0xffffffffu, rs, 1);
                rs += __shfl_xor_sync(0xffffffffu, rs, 2);
                rs += __shfl_xor_sync(0xffffffffu, rs, 4);
                rs += __shfl_xor_sync(0xffffffffu, rs, 8);
                lrow[i] = lrow[i] * cf + rs;
#pragma unroll
                for (int j = 0; j < 4; j++) o[i][j] *= cf;
            }

#pragma unroll
            for (int i = 0; i < 4; i++)
#pragma unroll
                for (int j = 0; j < 4; j++)
                    Ps[(tx * 4 + j) * 68 + (ty * 4 + i)] = s[i][j];
            __syncthreads();

#pragma unroll
            for (int c = 0; c < 64; c++) {
                float4 a  = *(const float4*)&Ps[c * 68 + ty * 4];
                float4 bb = *(const float4*)&Vs[c * 68 + tx * 4];
                const float af[4] = {a.x, a.y, a.z, a.w};
                const float bf[4] = {bb.x, bb.y, bb.z, bb.w};
#pragma unroll
                for (int i = 0; i < 4; i++)
#pragma unroll
                    for (int j = 0; j < 4; j++)
                        o[i][j] = fmaf(af[i], bf[j], o[i][j]);
            }
        }

#pragma unroll
        for (int i = 0; i < 4; i++) {
            const float inv = 1.f / lrow[i];
            float4 r4;
            r4.x = o[i][0] * inv;
            r4.y = o[i][1] * inv;
            r4.z = o[i][2] * inv;
            r4.w = o[i][3] * inv;
            *(float4*)&out[base + (size_t)(q0 + ty * 4 + i) * D_ + tx * 4] = r4;
        }
    }
}

// ---------------------------------------------------------------------------
extern "C" void kernel_launch(void* const* d_in, const int* in_sizes, int n_in,
                              void* d_out, int out_size)
{
    const float* x  = (const float*)d_in[0];
    // d_in[1] = atten_mask (strict upper triangular; handled analytically)
    const float* Wq = (const float*)d_in[2];
    const float* bq = (const float*)d_in[3];
    const float* Wk = (const float*)d_in[4];
    const float* bk = (const float*)d_in[5];
    const float* Wv = (const float*)d_in[6];
    const float* bv = (const float*)d_in[7];
    float* out = (float*)d_out;

    // 1) split fp32 -> bf16 hi/lo (x and all three W)
    const int n4 = (B_ * L_ * D_ + 3 * D_ * D_) / 4;
    decomp_kernel<<<n4 / 256, 256>>>(x, Wq, Wk, Wv);

    // 2) tensor-core QKV projections
    qkv_mma_kernel<<<dim3(D_ / 128, (B_ * L_) / 128, 3), 256>>>(bq, bk, bv);

    // 3) causal flash attention (fp32)
    const int smem = 4 * 64 * 68 * (int)sizeof(float);  // 69632 B
    cudaFuncSetAttribute(attn_kernel, cudaFuncAttributeMaxDynamicSharedMemorySize, smem);
    attn_kernel<<<dim3(L_ / 64 / 2, B_ * H_), 256, smem>>>(out);
}